// round 16
// baseline (speedup 1.0000x reference)
#include <cuda_runtime.h>
#include <cuda_fp16.h>
#include <cstdint>

#define M_TOTAL 16384
#define N_TOTAL 4096
#define K_TOTAL 4096
#define NSLOT   8

#define BM 128
#define BN 128
#define BK 64
#define STAGES 2
#define PADH 8
#define TSH (BK + PADH)        // 72 halves per row
#define ROWB (TSH * 2)         // 144 bytes per row
#define KT (K_TOTAL / BK)      // 64
#define ROWS_TOT (BM + BN)     // 256 rows per stage (A then B)
#define STAGE_B (ROWS_TOT * ROWB)  // 36864 bytes

// Scratch (allocation-free rule: __device__ globals)
__device__ __half g_W[(size_t)N_TOTAL * K_TOTAL];
__device__ __half g_X[(size_t)M_TOTAL * K_TOTAL];
__device__ float  g_b[N_TOTAL];

// ---------------------------------------------------------------------------
// Kernel 1: W = fp16(weight + sum_i (scale_i*wscale_i)*wq_i + (scale . wzp))
// ---------------------------------------------------------------------------
__global__ void compute_w_kernel(const float* __restrict__ weight,
                                 const int*   __restrict__ wq,
                                 const float* __restrict__ scale,
                                 const float* __restrict__ wscale,
                                 const int*   __restrict__ wzp) {
    const size_t nvec = (size_t)N_TOTAL * K_TOTAL / 4;
    size_t idx = (size_t)blockIdx.x * blockDim.x + threadIdx.x;
    if (idx >= nvec) return;

    float c[NSLOT];
    float z = 0.f;
#pragma unroll
    for (int i = 0; i < NSLOT; i++) {
        float s = scale[i];
        c[i] = s * wscale[i];
        z += s * (float)wzp[i];
    }
    float4 w = reinterpret_cast<const float4*>(weight)[idx];
    float ax = w.x + z, ay = w.y + z, az = w.z + z, aw = w.w + z;
#pragma unroll
    for (int i = 0; i < NSLOT; i++) {
        int4 q = reinterpret_cast<const int4*>(wq)[(size_t)i * nvec + idx];
        ax += c[i] * (float)q.x;
        ay += c[i] * (float)q.y;
        az += c[i] * (float)q.z;
        aw += c[i] * (float)q.w;
    }
    __half2 lo = __floats2half2_rn(ax, ay);
    __half2 hi = __floats2half2_rn(az, aw);
    reinterpret_cast<uint2*>(g_W)[idx] =
        make_uint2(*reinterpret_cast<uint32_t*>(&lo), *reinterpret_cast<uint32_t*>(&hi));
}

// ---------------------------------------------------------------------------
// Kernel 1b: X -> fp16
// ---------------------------------------------------------------------------
__global__ void round_x_kernel(const float* __restrict__ x) {
    const size_t nvec = (size_t)M_TOTAL * K_TOTAL / 4;
    size_t idx = (size_t)blockIdx.x * blockDim.x + threadIdx.x;
    if (idx >= nvec) return;
    float4 v = reinterpret_cast<const float4*>(x)[idx];
    __half2 lo = __floats2half2_rn(v.x, v.y);
    __half2 hi = __floats2half2_rn(v.z, v.w);
    reinterpret_cast<uint2*>(g_X)[idx] =
        make_uint2(*reinterpret_cast<uint32_t*>(&lo), *reinterpret_cast<uint32_t*>(&hi));
}

// ---------------------------------------------------------------------------
// Kernel 2: b = bias + sum_i scale_i*(bscale_i*bq_i + bzp_i)
// ---------------------------------------------------------------------------
__global__ void compute_b_kernel(const float* __restrict__ bias,
                                 const float* __restrict__ scale,
                                 const int*   __restrict__ bq,
                                 const float* __restrict__ bscale,
                                 const int*   __restrict__ bzp) {
    int j = blockIdx.x * blockDim.x + threadIdx.x;
    if (j >= N_TOTAL) return;
    float acc = bias[j];
#pragma unroll
    for (int i = 0; i < NSLOT; i++)
        acc += scale[i] * (bscale[i] * (float)bq[i * N_TOTAL + j] + (float)bzp[i]);
    g_b[j] = acc;
}

// ---------------------------------------------------------------------------
// Kernel 3: fp16 m16n8k16 GEMM, fp32 acc. CTA 128x128x64, 4 warps (2x2),
// warp tile 64x64, 128 threads, 2-stage cp.async, single barrier per k-tile.
// 3 CTAs/SM => 3 independent warps/SMSP; crossbar 0.0915 B/MAC < tensor roof.
// ---------------------------------------------------------------------------
extern __shared__ __half smem_h[];

__global__ void __launch_bounds__(128, 3)
gemm_fp16_kernel(float* __restrict__ OUT) {
    const int tid  = threadIdx.x;
    const int warp = tid >> 5;
    const int lane = tid & 31;
    const int wm = warp >> 1;   // 0..1 : 64 rows
    const int wn = warp & 1;    // 0..1 : 64 cols
    const int bm = blockIdx.y * BM;
    const int bn = blockIdx.x * BN;

    const uint32_t S_u = (uint32_t)__cvta_generic_to_shared(smem_h);

    // producer: 256 rows x 8 chunks(16B) = 2048 chunks / 128 thr = 16 each.
    // chunk c = tid + 128*j -> row = (tid>>3) + 16*j, colchunk = tid&7.
    // smem rows 0..127 = A, 128..255 = B (B row = smem row - 128).
    const int prow0 = tid >> 3;          // 0..15
    const int pcc   = tid & 7;
    const __half* aP = g_X + (size_t)(bm + prow0) * K_TOTAL + pcc * 8;
    const __half* bP = g_W + (size_t)(bn + prow0) * K_TOTAL + pcc * 8;
    const uint32_t d0 = S_u + prow0 * ROWB + pcc * 16;

    auto issue_tile = [&](int t) {
        const uint32_t sb = (uint32_t)((t & 1) * STAGE_B);
        const int kofs = t * BK;
#pragma unroll
        for (int j = 0; j < 8; j++) {   // A rows prow0 + 16j
            asm volatile("cp.async.cg.shared.global [%0], [%1], 16;\n"
                         :: "r"(d0 + sb + j * 16 * ROWB),
                            "l"(aP + (size_t)j * 16 * K_TOTAL + kofs));
        }
#pragma unroll
        for (int j = 0; j < 8; j++) {   // B rows prow0 + 16j -> smem rows 128+
            asm volatile("cp.async.cg.shared.global [%0], [%1], 16;\n"
                         :: "r"(d0 + sb + (128 + j * 16) * ROWB),
                            "l"(bP + (size_t)j * 16 * K_TOTAL + kofs));
        }
    };

    float acc[4][8][4];
#pragma unroll
    for (int mt = 0; mt < 4; mt++)
#pragma unroll
        for (int nt = 0; nt < 8; nt++)
#pragma unroll
            for (int r = 0; r < 4; r++) acc[mt][nt][r] = 0.f;

    // ldmatrix per-lane base offsets (bytes within a stage)
    const uint32_t a_lm = (uint32_t)((wm * 64 + (lane & 15)) * ROWB + (lane >> 4) * 16);
    const uint32_t b_lm = (uint32_t)((128 + wn * 64 + ((lane >> 4) * 8 + (lane & 7))) * ROWB
                                     + ((lane >> 3) & 1) * 16);

    const int q = lane >> 2;
    const int c = lane & 3;

    issue_tile(0);
    asm volatile("cp.async.commit_group;\n");

    for (int t = 0; t < KT; t++) {
        asm volatile("cp.async.wait_group 0;\n");
        __syncthreads();

        if (t + 1 < KT) {
            issue_tile(t + 1);
            asm volatile("cp.async.commit_group;\n");
        }

        const uint32_t sb = (uint32_t)((t & 1) * STAGE_B);
        const uint32_t aS = S_u + sb + a_lm;
        const uint32_t bS = S_u + sb + b_lm;

#pragma unroll
        for (int ks = 0; ks < 4; ks++) {
            const uint32_t kb = (uint32_t)ks * 32;
            uint32_t afr[4][4];
#pragma unroll
            for (int mt = 0; mt < 4; mt++) {
                asm volatile(
                    "ldmatrix.sync.aligned.m8n8.x4.shared.b16 {%0,%1,%2,%3}, [%4];"
                    : "=r"(afr[mt][0]), "=r"(afr[mt][1]),
                      "=r"(afr[mt][2]), "=r"(afr[mt][3])
                    : "r"(aS + mt * 16 * ROWB + kb));
            }
            // B in two 4-nt halves to keep frag live range small (reg cap 170)
#pragma unroll
            for (int h = 0; h < 2; h++) {
                uint32_t bfr[4][2];
#pragma unroll
                for (int pr = 0; pr < 2; pr++) {
                    asm volatile(
                        "ldmatrix.sync.aligned.m8n8.x4.shared.b16 {%0,%1,%2,%3}, [%4];"
                        : "=r"(bfr[2 * pr][0]), "=r"(bfr[2 * pr][1]),
                          "=r"(bfr[2 * pr + 1][0]), "=r"(bfr[2 * pr + 1][1])
                        : "r"(bS + (h * 2 + pr) * 16 * ROWB + kb));
                }
#pragma unroll
                for (int mt = 0; mt < 4; mt++) {
#pragma unroll
                    for (int j = 0; j < 4; j++) {
                        const int nt = h * 4 + j;
                        asm volatile(
                            "mma.sync.aligned.m16n8k16.row.col.f32.f16.f16.f32 "
                            "{%0,%1,%2,%3}, {%4,%5,%6,%7}, {%8,%9}, {%0,%1,%2,%3};\n"
                            : "+f"(acc[mt][nt][0]), "+f"(acc[mt][nt][1]),
                              "+f"(acc[mt][nt][2]), "+f"(acc[mt][nt][3])
                            : "r"(afr[mt][0]), "r"(afr[mt][1]),
                              "r"(afr[mt][2]), "r"(afr[mt][3]),
                              "r"(bfr[j][0]), "r"(bfr[j][1]));
                    }
                }
            }
        }
    }

    // epilogue: bias + store (C fragment layout of m16n8)
#pragma unroll
    for (int mt = 0; mt < 4; mt++) {
        const int row0 = bm + wm * 64 + mt * 16 + q;
#pragma unroll
        for (int nt = 0; nt < 8; nt++) {
            const int col = bn + wn * 64 + nt * 8 + c * 2;
            const float b0 = g_b[col];
            const float b1 = g_b[col + 1];
            float2 v0 = make_float2(acc[mt][nt][0] + b0, acc[mt][nt][1] + b1);
            float2 v1 = make_float2(acc[mt][nt][2] + b0, acc[mt][nt][3] + b1);
            *reinterpret_cast<float2*>(OUT + (size_t)row0 * N_TOTAL + col) = v0;
            *reinterpret_cast<float2*>(OUT + (size_t)(row0 + 8) * N_TOTAL + col) = v1;
        }
    }
}

// ---------------------------------------------------------------------------
extern "C" void kernel_launch(void* const* d_in, const int* in_sizes, int n_in,
                              void* d_out, int out_size) {
    const float* x      = (const float*)d_in[0];
    const float* weight = (const float*)d_in[1];
    const float* bias   = (const float*)d_in[2];
    const float* scale  = (const float*)d_in[3];
    const int*   wq     = (const int*)  d_in[4];
    const float* wscale = (const float*)d_in[5];
    const int*   wzp    = (const int*)  d_in[6];
    const int*   bq     = (const int*)  d_in[7];
    const float* bscale = (const float*)d_in[8];
    const int*   bzp    = (const int*)  d_in[9];
    float* out = (float*)d_out;

    {
        const size_t nvec = (size_t)N_TOTAL * K_TOTAL / 4;
        compute_w_kernel<<<(int)((nvec + 255) / 256), 256>>>(weight, wq, scale, wscale, wzp);
    }
    {
        const size_t nvec = (size_t)M_TOTAL * K_TOTAL / 4;
        round_x_kernel<<<(int)((nvec + 255) / 256), 256>>>(x);
    }
    compute_b_kernel<<<(N_TOTAL + 255) / 256, 256>>>(bias, scale, bq, bscale, bzp);

    {
        int smem_bytes = STAGES * STAGE_B;   // 73728
        cudaFuncSetAttribute(gemm_fp16_kernel,
                             cudaFuncAttributeMaxDynamicSharedMemorySize, smem_bytes);
        dim3 grid(N_TOTAL / BN, M_TOTAL / BM);   // (32, 128)
        gemm_fp16_kernel<<<grid, 128, smem_bytes>>>(out);
    }
}

// round 17
// speedup vs baseline: 1.0345x; 1.0345x over previous
#include <cuda_runtime.h>
#include <cuda_fp16.h>
#include <cstdint>

#define M_TOTAL 16384
#define N_TOTAL 4096
#define K_TOTAL 4096
#define NSLOT   8

#define BM 128
#define BN 128
#define BK 64
#define STAGES 2
#define PADH 8
#define TSH (BK + PADH)        // 72 halves per row
#define ROWB (TSH * 2)         // 144 bytes per row
#define KT (K_TOTAL / BK)      // 64
#define ROWS_TOT (BM + BN)     // 256 rows per stage (A then B)
#define STAGE_B (ROWS_TOT * ROWB)  // 36864 bytes

// Scratch (allocation-free rule: __device__ globals)
__device__ __half g_W[(size_t)N_TOTAL * K_TOTAL];
__device__ __half g_X[(size_t)M_TOTAL * K_TOTAL];
__device__ float  g_b[N_TOTAL];

// ---------------------------------------------------------------------------
// Kernel 1: W = fp16(weight + sum_i (scale_i*wscale_i)*wq_i + (scale . wzp))
// ---------------------------------------------------------------------------
__global__ void compute_w_kernel(const float* __restrict__ weight,
                                 const int*   __restrict__ wq,
                                 const float* __restrict__ scale,
                                 const float* __restrict__ wscale,
                                 const int*   __restrict__ wzp) {
    const size_t nvec = (size_t)N_TOTAL * K_TOTAL / 4;
    size_t idx = (size_t)blockIdx.x * blockDim.x + threadIdx.x;
    if (idx >= nvec) return;

    float c[NSLOT];
    float z = 0.f;
#pragma unroll
    for (int i = 0; i < NSLOT; i++) {
        float s = scale[i];
        c[i] = s * wscale[i];
        z += s * (float)wzp[i];
    }
    float4 w = reinterpret_cast<const float4*>(weight)[idx];
    float ax = w.x + z, ay = w.y + z, az = w.z + z, aw = w.w + z;
#pragma unroll
    for (int i = 0; i < NSLOT; i++) {
        int4 q = reinterpret_cast<const int4*>(wq)[(size_t)i * nvec + idx];
        ax += c[i] * (float)q.x;
        ay += c[i] * (float)q.y;
        az += c[i] * (float)q.z;
        aw += c[i] * (float)q.w;
    }
    __half2 lo = __floats2half2_rn(ax, ay);
    __half2 hi = __floats2half2_rn(az, aw);
    reinterpret_cast<uint2*>(g_W)[idx] =
        make_uint2(*reinterpret_cast<uint32_t*>(&lo), *reinterpret_cast<uint32_t*>(&hi));
}

// ---------------------------------------------------------------------------
// Kernel 1b: X -> fp16
// ---------------------------------------------------------------------------
__global__ void round_x_kernel(const float* __restrict__ x) {
    const size_t nvec = (size_t)M_TOTAL * K_TOTAL / 4;
    size_t idx = (size_t)blockIdx.x * blockDim.x + threadIdx.x;
    if (idx >= nvec) return;
    float4 v = reinterpret_cast<const float4*>(x)[idx];
    __half2 lo = __floats2half2_rn(v.x, v.y);
    __half2 hi = __floats2half2_rn(v.z, v.w);
    reinterpret_cast<uint2*>(g_X)[idx] =
        make_uint2(*reinterpret_cast<uint32_t*>(&lo), *reinterpret_cast<uint32_t*>(&hi));
}

// ---------------------------------------------------------------------------
// Kernel 2: b = bias + sum_i scale_i*(bscale_i*bq_i + bzp_i)
// ---------------------------------------------------------------------------
__global__ void compute_b_kernel(const float* __restrict__ bias,
                                 const float* __restrict__ scale,
                                 const int*   __restrict__ bq,
                                 const float* __restrict__ bscale,
                                 const int*   __restrict__ bzp) {
    int j = blockIdx.x * blockDim.x + threadIdx.x;
    if (j >= N_TOTAL) return;
    float acc = bias[j];
#pragma unroll
    for (int i = 0; i < NSLOT; i++)
        acc += scale[i] * (bscale[i] * (float)bq[i * N_TOTAL + j] + (float)bzp[i]);
    g_b[j] = acc;
}

// ---------------------------------------------------------------------------
// Kernel 3: fp16 m16n8k16 GEMM, fp32 acc. CTA 128x128x64, 8 warps (2x4),
// warp tile 64x32, 256 threads, 2-stage cp.async, single barrier per k-tile.
// 2 CTAs/SM => 4 warps/SMSP; B/MAC 0.123 (roof 1041 MACs/cyc/SM).
// ---------------------------------------------------------------------------
extern __shared__ __half smem_h[];

__global__ void __launch_bounds__(256, 2)
gemm_fp16_kernel(float* __restrict__ OUT) {
    const int tid  = threadIdx.x;
    const int warp = tid >> 5;
    const int lane = tid & 31;
    const int wm = warp >> 2;   // 0..1 : 64 rows
    const int wn = warp & 3;    // 0..3 : 32 cols
    const int bm = blockIdx.y * BM;
    const int bn = blockIdx.x * BN;

    const uint32_t S_u = (uint32_t)__cvta_generic_to_shared(smem_h);

    // producer: 256 rows x 8 chunks(16B) = 2048 chunks / 256 thr = 8 each.
    // chunk c = tid + 256*j -> row = (tid>>3) + 32*j, colchunk = tid&7.
    // smem rows 0..127 = A, 128..255 = B (B row = smem row - 128).
    const int prow0 = tid >> 3;          // 0..31
    const int pcc   = tid & 7;
    const __half* aP = g_X + (size_t)(bm + prow0) * K_TOTAL + pcc * 8;
    const __half* bP = g_W + (size_t)(bn + prow0) * K_TOTAL + pcc * 8;
    const uint32_t d0 = S_u + prow0 * ROWB + pcc * 16;

    auto issue_tile = [&](int t) {
        const uint32_t sb = (uint32_t)((t & 1) * STAGE_B);
        const int kofs = t * BK;
#pragma unroll
        for (int j = 0; j < 4; j++) {   // A rows prow0 + 32j
            asm volatile("cp.async.cg.shared.global [%0], [%1], 16;\n"
                         :: "r"(d0 + sb + j * 32 * ROWB),
                            "l"(aP + (size_t)j * 32 * K_TOTAL + kofs));
        }
#pragma unroll
        for (int j = 0; j < 4; j++) {   // B rows prow0 + 32j -> smem rows 128+
            asm volatile("cp.async.cg.shared.global [%0], [%1], 16;\n"
                         :: "r"(d0 + sb + (128 + j * 32) * ROWB),
                            "l"(bP + (size_t)j * 32 * K_TOTAL + kofs));
        }
    };

    float acc[4][4][4];
#pragma unroll
    for (int mt = 0; mt < 4; mt++)
#pragma unroll
        for (int nt = 0; nt < 4; nt++)
#pragma unroll
            for (int r = 0; r < 4; r++) acc[mt][nt][r] = 0.f;

    // ldmatrix per-lane base offsets (bytes within a stage)
    const uint32_t a_lm = (uint32_t)((wm * 64 + (lane & 15)) * ROWB + (lane >> 4) * 16);
    const uint32_t b_lm = (uint32_t)((128 + wn * 32 + ((lane >> 4) * 8 + (lane & 7))) * ROWB
                                     + ((lane >> 3) & 1) * 16);

    const int q = lane >> 2;
    const int c = lane & 3;

    issue_tile(0);
    asm volatile("cp.async.commit_group;\n");

    for (int t = 0; t < KT; t++) {
        asm volatile("cp.async.wait_group 0;\n");
        __syncthreads();

        if (t + 1 < KT) {
            issue_tile(t + 1);
            asm volatile("cp.async.commit_group;\n");
        }

        const uint32_t sb = (uint32_t)((t & 1) * STAGE_B);
        const uint32_t aS = S_u + sb + a_lm;
        const uint32_t bS = S_u + sb + b_lm;

#pragma unroll
        for (int ks = 0; ks < 4; ks++) {
            const uint32_t kb = (uint32_t)ks * 32;
            uint32_t afr[4][4];
#pragma unroll
            for (int mt = 0; mt < 4; mt++) {
                asm volatile(
                    "ldmatrix.sync.aligned.m8n8.x4.shared.b16 {%0,%1,%2,%3}, [%4];"
                    : "=r"(afr[mt][0]), "=r"(afr[mt][1]),
                      "=r"(afr[mt][2]), "=r"(afr[mt][3])
                    : "r"(aS + mt * 16 * ROWB + kb));
            }
            uint32_t bfr[4][2];
#pragma unroll
            for (int pr = 0; pr < 2; pr++) {
                asm volatile(
                    "ldmatrix.sync.aligned.m8n8.x4.shared.b16 {%0,%1,%2,%3}, [%4];"
                    : "=r"(bfr[2 * pr][0]), "=r"(bfr[2 * pr][1]),
                      "=r"(bfr[2 * pr + 1][0]), "=r"(bfr[2 * pr + 1][1])
                    : "r"(bS + pr * 16 * ROWB + kb));
            }
#pragma unroll
            for (int mt = 0; mt < 4; mt++) {
#pragma unroll
                for (int nt = 0; nt < 4; nt++) {
                    asm volatile(
                        "mma.sync.aligned.m16n8k16.row.col.f32.f16.f16.f32 "
                        "{%0,%1,%2,%3}, {%4,%5,%6,%7}, {%8,%9}, {%0,%1,%2,%3};\n"
                        : "+f"(acc[mt][nt][0]), "+f"(acc[mt][nt][1]),
                          "+f"(acc[mt][nt][2]), "+f"(acc[mt][nt][3])
                        : "r"(afr[mt][0]), "r"(afr[mt][1]),
                          "r"(afr[mt][2]), "r"(afr[mt][3]),
                          "r"(bfr[nt][0]), "r"(bfr[nt][1]));
                }
            }
        }
    }

    // epilogue: bias + store (C fragment layout of m16n8)
#pragma unroll
    for (int mt = 0; mt < 4; mt++) {
        const int row0 = bm + wm * 64 + mt * 16 + q;
#pragma unroll
        for (int nt = 0; nt < 4; nt++) {
            const int col = bn + wn * 32 + nt * 8 + c * 2;
            const float b0 = g_b[col];
            const float b1 = g_b[col + 1];
            float2 v0 = make_float2(acc[mt][nt][0] + b0, acc[mt][nt][1] + b1);
            float2 v1 = make_float2(acc[mt][nt][2] + b0, acc[mt][nt][3] + b1);
            *reinterpret_cast<float2*>(OUT + (size_t)row0 * N_TOTAL + col) = v0;
            *reinterpret_cast<float2*>(OUT + (size_t)(row0 + 8) * N_TOTAL + col) = v1;
        }
    }
}

// ---------------------------------------------------------------------------
extern "C" void kernel_launch(void* const* d_in, const int* in_sizes, int n_in,
                              void* d_out, int out_size) {
    const float* x      = (const float*)d_in[0];
    const float* weight = (const float*)d_in[1];
    const float* bias   = (const float*)d_in[2];
    const float* scale  = (const float*)d_in[3];
    const int*   wq     = (const int*)  d_in[4];
    const float* wscale = (const float*)d_in[5];
    const int*   wzp    = (const int*)  d_in[6];
    const int*   bq     = (const int*)  d_in[7];
    const float* bscale = (const float*)d_in[8];
    const int*   bzp    = (const int*)  d_in[9];
    float* out = (float*)d_out;

    {
        const size_t nvec = (size_t)N_TOTAL * K_TOTAL / 4;
        compute_w_kernel<<<(int)((nvec + 255) / 256), 256>>>(weight, wq, scale, wscale, wzp);
    }
    {
        const size_t nvec = (size_t)M_TOTAL * K_TOTAL / 4;
        round_x_kernel<<<(int)((nvec + 255) / 256), 256>>>(x);
    }
    compute_b_kernel<<<(N_TOTAL + 255) / 256, 256>>>(bias, scale, bq, bscale, bzp);

    {
        int smem_bytes = STAGES * STAGE_B;   // 73728
        cudaFuncSetAttribute(gemm_fp16_kernel,
                             cudaFuncAttributeMaxDynamicSharedMemorySize, smem_bytes);
        dim3 grid(N_TOTAL / BN, M_TOTAL / BM);   // (32, 128)
        gemm_fp16_kernel<<<grid, 256, smem_bytes>>>(out);
    }
}